// round 3
// baseline (speedup 1.0000x reference)
#include <cuda_runtime.h>

// Problem constants
static constexpr int H    = 768;
static constexpr int B    = 64;
static constexpr int S1   = 513;
static constexpr int S    = 512;
static constexpr int NT   = 4;   // number of CRF states (T)
static constexpr int TSTART = 2;
static constexpr int TSTOP  = 3;

// Output layout (flattened tuple, float32):
// [isqa_pred(64), crf_pred(64*512), isqa_loss(1), crf_loss(1), tags(64*512), IsQA(64)]
static constexpr int OFF_IPRED = 0;
static constexpr int OFF_CPRED = 64;
static constexpr int OFF_ILOSS = 64 + B * S;          // 32832
static constexpr int OFF_CLOSS = OFF_ILOSS + 1;       // 32833
static constexpr int OFF_TAGS  = OFF_CLOSS + 1;       // 32834
static constexpr int OFF_ISQA  = OFF_TAGS + B * S;    // 65602

// Scratch (device globals; no dynamic allocation allowed)
__device__ float g_feats[B * S * NT];   // 512 KB
__device__ float g_logits[B * 2];
__device__ float g_dloss[B];
__device__ float g_iloss[B];

// ---------------------------------------------------------------------------
// Kernel 1: emission features (GEMV vs crf_W) + isqa logits (token 0 vs fc2_W)
// One warp per row; crf_W held in registers; float4 vectorized.
// ---------------------------------------------------------------------------
__global__ void k_feats(const float* __restrict__ emb,
                        const float* __restrict__ fc2_W,
                        const float* __restrict__ fc2_b,
                        const float* __restrict__ crf_W,
                        const float* __restrict__ crf_b) {
    const int lane = threadIdx.x & 31;
    const int gw   = (blockIdx.x * blockDim.x + threadIdx.x) >> 5;
    const int nw   = (gridDim.x * blockDim.x) >> 5;

    // Load this lane's slice of crf_W into registers: 4 rows x 24 floats
    float4 w[NT][6];
#pragma unroll
    for (int t = 0; t < NT; t++)
#pragma unroll
        for (int k = 0; k < 6; k++)
            w[t][k] = *reinterpret_cast<const float4*>(crf_W + t * H + lane * 24 + k * 4);

    float cb[NT];
#pragma unroll
    for (int t = 0; t < NT; t++) cb[t] = crf_b[t];

    for (int r = gw; r < B * S1; r += nw) {
        const int b = r / S1;
        const int s = r - b * S1;
        const float4* e = reinterpret_cast<const float4*>(emb + (size_t)r * H) + lane * 6;
        float4 ev[6];
#pragma unroll
        for (int k = 0; k < 6; k++) ev[k] = e[k];

        if (s == 0) {
            // isqa logits for token 0
            float a0 = 0.f, a1 = 0.f;
#pragma unroll
            for (int k = 0; k < 6; k++) {
                float4 w0 = *reinterpret_cast<const float4*>(fc2_W + 0 * H + lane * 24 + k * 4);
                float4 w1 = *reinterpret_cast<const float4*>(fc2_W + 1 * H + lane * 24 + k * 4);
                a0 += ev[k].x * w0.x + ev[k].y * w0.y + ev[k].z * w0.z + ev[k].w * w0.w;
                a1 += ev[k].x * w1.x + ev[k].y * w1.y + ev[k].z * w1.z + ev[k].w * w1.w;
            }
#pragma unroll
            for (int off = 16; off; off >>= 1) {
                a0 += __shfl_xor_sync(0xFFFFFFFFu, a0, off);
                a1 += __shfl_xor_sync(0xFFFFFFFFu, a1, off);
            }
            if (lane == 0) {
                g_logits[b * 2 + 0] = a0 + fc2_b[0];
                g_logits[b * 2 + 1] = a1 + fc2_b[1];
            }
        } else {
            float acc[NT] = {0.f, 0.f, 0.f, 0.f};
#pragma unroll
            for (int k = 0; k < 6; k++) {
#pragma unroll
                for (int t = 0; t < NT; t++) {
                    acc[t] += ev[k].x * w[t][k].x + ev[k].y * w[t][k].y +
                              ev[k].z * w[t][k].z + ev[k].w * w[t][k].w;
                }
            }
#pragma unroll
            for (int off = 16; off; off >>= 1)
#pragma unroll
                for (int t = 0; t < NT; t++)
                    acc[t] += __shfl_xor_sync(0xFFFFFFFFu, acc[t], off);
            if (lane == 0) {
                float4 o = make_float4(acc[0] + cb[0], acc[1] + cb[1],
                                       acc[2] + cb[2], acc[3] + cb[3]);
                *reinterpret_cast<float4*>(g_feats + (size_t)(b * S + (s - 1)) * NT) = o;
            }
        }
    }
}

// ---------------------------------------------------------------------------
// Kernel 2: per-batch CRF forward (log-partition), Viterbi + backtrace,
// gold score, isqa loss/pred, tags echo. One block per batch, 128 threads.
// ---------------------------------------------------------------------------
__global__ void k_crf(const int* __restrict__ labels,
                      const int* __restrict__ isqa,
                      const float* __restrict__ trans,
                      float* __restrict__ out) {
    __shared__ float sf[S * NT];     // feats for this batch
    __shared__ float sd[S * NT];     // viterbi deltas
    __shared__ int   stag[S];
    __shared__ int   spath[S];
    __shared__ float strn[16];
    __shared__ float sZ, sGold;

    const int b   = blockIdx.x;
    const int tid = threadIdx.x;

    // Stage feats, tags, trans into shared memory
    const float4* fsrc = reinterpret_cast<const float4*>(g_feats + (size_t)b * S * NT);
    float4* f4 = reinterpret_cast<float4*>(sf);
    for (int i = tid; i < S; i += blockDim.x) f4[i] = fsrc[i];
    for (int i = tid; i < S; i += blockDim.x) {
        int tg = labels[b * S1 + 1 + i];
        stag[i] = tg;
        out[OFF_TAGS + b * S + i] = (float)tg;
    }
    if (tid < 16) strn[tid] = trans[tid];
    __syncthreads();

    const int warp = tid >> 5, lane = tid & 31;

    if (warp == 0 && lane == 0) {
        // ---- Forward recursion: log-partition Z ----
        float Tm[16], E[16];
#pragma unroll
        for (int i = 0; i < 16; i++) Tm[i] = strn[i];
#pragma unroll
        for (int i = 0; i < 16; i++) E[i] = __expf(Tm[i]);
        float a0 = sf[0] + Tm[8], a1 = sf[1] + Tm[9];
        float a2 = sf[2] + Tm[10], a3 = sf[3] + Tm[11];
        for (int s = 1; s < S; s++) {
            float m  = fmaxf(fmaxf(a0, a1), fmaxf(a2, a3));
            float e0 = __expf(a0 - m), e1 = __expf(a1 - m);
            float e2 = __expf(a2 - m), e3 = __expf(a3 - m);
            float4 f = reinterpret_cast<const float4*>(sf)[s];
            float s0 = e0 * E[0] + e1 * E[4] + e2 * E[8]  + e3 * E[12];
            float s1 = e0 * E[1] + e1 * E[5] + e2 * E[9]  + e3 * E[13];
            float s2 = e0 * E[2] + e1 * E[6] + e2 * E[10] + e3 * E[14];
            float s3 = e0 * E[3] + e1 * E[7] + e2 * E[11] + e3 * E[15];
            a0 = m + __logf(s0) + f.x;
            a1 = m + __logf(s1) + f.y;
            a2 = m + __logf(s2) + f.z;
            a3 = m + __logf(s3) + f.w;
        }
        a0 += Tm[3]; a1 += Tm[7]; a2 += Tm[11]; a3 += Tm[15];
        float m = fmaxf(fmaxf(a0, a1), fmaxf(a2, a3));
        sZ = m + __logf(__expf(a0 - m) + __expf(a1 - m) +
                        __expf(a2 - m) + __expf(a3 - m));
    } else if (warp == 1 && lane == 0) {
        // ---- Viterbi forward (store deltas) + backtrace ----
        float Tm[16];
#pragma unroll
        for (int i = 0; i < 16; i++) Tm[i] = strn[i];
        float d0 = sf[0] + Tm[8], d1 = sf[1] + Tm[9];
        float d2 = sf[2] + Tm[10], d3 = sf[3] + Tm[11];
        reinterpret_cast<float4*>(sd)[0] = make_float4(d0, d1, d2, d3);
        for (int s = 1; s < S; s++) {
            float4 f = reinterpret_cast<const float4*>(sf)[s];
            float n0 = fmaxf(fmaxf(d0 + Tm[0], d1 + Tm[4]), fmaxf(d2 + Tm[8],  d3 + Tm[12])) + f.x;
            float n1 = fmaxf(fmaxf(d0 + Tm[1], d1 + Tm[5]), fmaxf(d2 + Tm[9],  d3 + Tm[13])) + f.y;
            float n2 = fmaxf(fmaxf(d0 + Tm[2], d1 + Tm[6]), fmaxf(d2 + Tm[10], d3 + Tm[14])) + f.z;
            float n3 = fmaxf(fmaxf(d0 + Tm[3], d1 + Tm[7]), fmaxf(d2 + Tm[11], d3 + Tm[15])) + f.w;
            d0 = n0; d1 = n1; d2 = n2; d3 = n3;
            reinterpret_cast<float4*>(sd)[s] = make_float4(d0, d1, d2, d3);
        }
        // last tag (first-index argmax)
        float v0 = d0 + Tm[3], v1 = d1 + Tm[7], v2 = d2 + Tm[11], v3 = d3 + Tm[15];
        int lt = 0; float best = v0;
        if (v1 > best) { best = v1; lt = 1; }
        if (v2 > best) { best = v2; lt = 2; }
        if (v3 > best) { best = v3; lt = 3; }
        spath[S - 1] = lt;
        int tag = lt;
        for (int t = S - 1; t >= 1; t--) {
            float4 dp = reinterpret_cast<const float4*>(sd)[t - 1];
            float c0 = strn[tag], c1 = strn[4 + tag];
            float c2 = strn[8 + tag], c3 = strn[12 + tag];
            float b0 = dp.x + c0, b1 = dp.y + c1, b2 = dp.z + c2, b3 = dp.w + c3;
            int a = 0; float bb = b0;
            if (b1 > bb) { bb = b1; a = 1; }
            if (b2 > bb) { bb = b2; a = 2; }
            if (b3 > bb) { bb = b3; a = 3; }
            tag = a; spath[t - 1] = a;
        }
    } else if (warp == 2) {
        // ---- Gold score + per-batch isqa ----
        float em = 0.f, tr = 0.f;
        for (int s = lane; s < S; s += 32)     em += sf[s * NT + stag[s]];
        for (int s = lane; s < S - 1; s += 32) tr += strn[stag[s] * NT + stag[s + 1]];
        float v = em + tr;
#pragma unroll
        for (int off = 16; off; off >>= 1) v += __shfl_xor_sync(0xFFFFFFFFu, v, off);
        if (lane == 0) {
            sGold = v + strn[TSTART * NT + stag[0]] + strn[stag[S - 1] * NT + TSTOP];
            float l0 = g_logits[b * 2], l1 = g_logits[b * 2 + 1];
            float mm  = fmaxf(l0, l1);
            float lse = mm + __logf(__expf(l0 - mm) + __expf(l1 - mm));
            int y = isqa[b];
            g_iloss[b] = -((y ? l1 : l0) - lse);
            out[OFF_IPRED + b] = (l1 > l0) ? 1.0f : 0.0f;
            out[OFF_ISQA + b] = (float)y;
        }
    }
    __syncthreads();
    if (tid == 0) g_dloss[b] = sZ - sGold;
    for (int i = tid; i < S; i += blockDim.x)
        out[OFF_CPRED + b * S + i] = (float)spath[i];
}

// ---------------------------------------------------------------------------
// Kernel 3: reduce per-batch losses to the two scalar outputs
// ---------------------------------------------------------------------------
__global__ void k_final(float* __restrict__ out) {
    const int tid = threadIdx.x;   // 64 threads
    float d  = g_dloss[tid];
    float il = g_iloss[tid];
#pragma unroll
    for (int off = 16; off; off >>= 1) {
        d  += __shfl_xor_sync(0xFFFFFFFFu, d, off);
        il += __shfl_xor_sync(0xFFFFFFFFu, il, off);
    }
    __shared__ float sd2[2], si2[2];
    if ((tid & 31) == 0) { sd2[tid >> 5] = d; si2[tid >> 5] = il; }
    __syncthreads();
    if (tid == 0) {
        out[OFF_CLOSS] = (sd2[0] + sd2[1]) * (1.0f / 64.0f);
        out[OFF_ILOSS] = (si2[0] + si2[1]) * (1.0f / 64.0f);
    }
}

// ---------------------------------------------------------------------------
extern "C" void kernel_launch(void* const* d_in, const int* in_sizes, int n_in,
                              void* d_out, int out_size) {
    const float* emb    = (const float*)d_in[0];
    const int*   labels = (const int*)d_in[1];
    const int*   isqa   = (const int*)d_in[2];
    const float* fc2_W  = (const float*)d_in[3];
    const float* fc2_b  = (const float*)d_in[4];
    const float* crf_W  = (const float*)d_in[5];
    const float* crf_b  = (const float*)d_in[6];
    const float* trans  = (const float*)d_in[7];
    float* out = (float*)d_out;

    k_feats<<<512, 256>>>(emb, fc2_W, fc2_b, crf_W, crf_b);
    k_crf<<<B, 128>>>(labels, isqa, trans, out);
    k_final<<<1, 64>>>(out);
}

// round 4
// speedup vs baseline: 1.0651x; 1.0651x over previous
#include <cuda_runtime.h>

// Problem constants
static constexpr int H    = 768;
static constexpr int B    = 64;
static constexpr int S1   = 513;
static constexpr int S    = 512;
static constexpr int NT   = 4;   // number of CRF states (T)
static constexpr int TSTART = 2;
static constexpr int TSTOP  = 3;

// Output layout (flattened tuple, float32):
// [isqa_pred(64), crf_pred(64*512), isqa_loss(1), crf_loss(1), tags(64*512), IsQA(64)]
static constexpr int OFF_IPRED = 0;
static constexpr int OFF_CPRED = 64;
static constexpr int OFF_ILOSS = 64 + B * S;          // 32832
static constexpr int OFF_CLOSS = OFF_ILOSS + 1;       // 32833
static constexpr int OFF_TAGS  = OFF_CLOSS + 1;       // 32834
static constexpr int OFF_ISQA  = OFF_TAGS + B * S;    // 65602

// Scratch (device globals; no dynamic allocation allowed)
__device__ float g_feats[B * S * NT];   // 512 KB
__device__ float g_logits[B * 2];
__device__ float g_dloss[B];
__device__ float g_iloss[B];

// ---------------------------------------------------------------------------
// Kernel 1: emission features (GEMV vs crf_W) + isqa logits (token 0 vs fc2_W)
// One warp per row; crf_W staged in padded shared memory (conflict-free
// LDS.128, lane stride 100 floats); float4 vectorized; low register count
// for high occupancy / memory-level parallelism.
// ---------------------------------------------------------------------------
__global__ void __launch_bounds__(256, 3)
k_feats(const float* __restrict__ emb,
        const float* __restrict__ fc2_W,
        const float* __restrict__ fc2_b,
        const float* __restrict__ crf_W,
        const float* __restrict__ crf_b) {
    // Per-lane slice of crf_W: 96 floats, padded to 100 for bank-conflict-free
    // LDS.128 (stride 100 floats = 4 banks per lane step).
    __shared__ float sw[32 * 100];      // 12.8 KB
    __shared__ float scb[NT];

    const int tid = threadIdx.x;
    // Stage crf_W into padded per-lane layout:
    // sw[lane*100 + t*24 + c] = crf_W[t*768 + lane*24 + c]
    for (int j = tid; j < 32 * 96; j += blockDim.x) {
        const int lane = j / 96;
        const int q    = j - lane * 96;     // q = t*24 + c
        const int t    = q / 24;
        const int c    = q - t * 24;
        sw[lane * 100 + q] = crf_W[t * H + lane * 24 + c];
    }
    if (tid < NT) scb[tid] = crf_b[tid];
    __syncthreads();

    const int lane = tid & 31;
    const int gw   = (blockIdx.x * blockDim.x + tid) >> 5;
    const int nw   = (gridDim.x * blockDim.x) >> 5;
    const float4* wl = reinterpret_cast<const float4*>(sw + lane * 100);

    for (int r = gw; r < B * S1; r += nw) {
        const int b = r / S1;
        const int s = r - b * S1;
        const float4* e = reinterpret_cast<const float4*>(emb + (size_t)r * H) + lane * 6;
        float4 ev[6];
#pragma unroll
        for (int k = 0; k < 6; k++) ev[k] = e[k];

        if (s == 0) {
            // isqa logits for token 0 (rare path: 64 of 32832 rows)
            float a0 = 0.f, a1 = 0.f;
#pragma unroll
            for (int k = 0; k < 6; k++) {
                float4 w0 = *reinterpret_cast<const float4*>(fc2_W + 0 * H + lane * 24 + k * 4);
                float4 w1 = *reinterpret_cast<const float4*>(fc2_W + 1 * H + lane * 24 + k * 4);
                a0 += ev[k].x * w0.x + ev[k].y * w0.y + ev[k].z * w0.z + ev[k].w * w0.w;
                a1 += ev[k].x * w1.x + ev[k].y * w1.y + ev[k].z * w1.z + ev[k].w * w1.w;
            }
#pragma unroll
            for (int off = 16; off; off >>= 1) {
                a0 += __shfl_xor_sync(0xFFFFFFFFu, a0, off);
                a1 += __shfl_xor_sync(0xFFFFFFFFu, a1, off);
            }
            if (lane == 0) {
                g_logits[b * 2 + 0] = a0 + fc2_b[0];
                g_logits[b * 2 + 1] = a1 + fc2_b[1];
            }
        } else {
            float acc[NT] = {0.f, 0.f, 0.f, 0.f};
#pragma unroll
            for (int t = 0; t < NT; t++) {
#pragma unroll
                for (int k = 0; k < 6; k++) {
                    float4 w = wl[t * 6 + k];
                    acc[t] += ev[k].x * w.x + ev[k].y * w.y +
                              ev[k].z * w.z + ev[k].w * w.w;
                }
            }
#pragma unroll
            for (int off = 16; off; off >>= 1)
#pragma unroll
                for (int t = 0; t < NT; t++)
                    acc[t] += __shfl_xor_sync(0xFFFFFFFFu, acc[t], off);
            if (lane == 0) {
                float4 o = make_float4(acc[0] + scb[0], acc[1] + scb[1],
                                       acc[2] + scb[2], acc[3] + scb[3]);
                *reinterpret_cast<float4*>(g_feats + (size_t)(b * S + (s - 1)) * NT) = o;
            }
        }
    }
}

// ---------------------------------------------------------------------------
// Kernel 2: per-batch CRF. One block per batch, 128 threads.
//  warp0/lane0: forward log-partition via LINEAR-domain scan with periodic
//               renormalization (exp(feats) precomputed block-wide).
//  warp1/lane0: Viterbi forward storing packed 2-bit backpointers + backtrace.
//  warp2      : gold score + isqa loss/pred.
// ---------------------------------------------------------------------------
__global__ void k_crf(const int* __restrict__ labels,
                      const int* __restrict__ isqa,
                      const float* __restrict__ trans,
                      float* __restrict__ out) {
    __shared__ float sf[S * NT];     // feats (log domain)
    __shared__ float sef[S * NT];    // exp(feats)
    __shared__ int   sbp[S];         // packed backpointers (2 bits/state)
    __shared__ int   stag[S];
    __shared__ int   spath[S];
    __shared__ float strn[16];
    __shared__ float sZ, sGold;

    const int b   = blockIdx.x;
    const int tid = threadIdx.x;

    // Stage feats, exp(feats), tags, trans
    const float4* fsrc = reinterpret_cast<const float4*>(g_feats + (size_t)b * S * NT);
    float4* f4  = reinterpret_cast<float4*>(sf);
    float4* ef4 = reinterpret_cast<float4*>(sef);
    for (int i = tid; i < S; i += blockDim.x) {
        float4 v = fsrc[i];
        f4[i] = v;
        ef4[i] = make_float4(__expf(v.x), __expf(v.y), __expf(v.z), __expf(v.w));
    }
    for (int i = tid; i < S; i += blockDim.x) {
        int tg = labels[b * S1 + 1 + i];
        stag[i] = tg;
        out[OFF_TAGS + b * S + i] = (float)tg;
    }
    if (tid < 16) strn[tid] = trans[tid];
    __syncthreads();

    const int warp = tid >> 5, lane = tid & 31;

    if (warp == 0 && lane == 0) {
        // ---- Forward recursion in linear domain with renorm every 8 steps ----
        float E[16];
#pragma unroll
        for (int i = 0; i < 16; i++) E[i] = __expf(strn[i]);
        // alpha0_j = exp(feat0_j + trans[START][j])
        float4 ef0 = reinterpret_cast<const float4*>(sef)[0];
        float a0 = ef0.x * E[8],  a1 = ef0.y * E[9];
        float a2 = ef0.z * E[10], a3 = ef0.w * E[11];
        float lz = 0.f;

#pragma unroll 1
        for (int c = 0; c < 63; c++) {           // steps 1..504
#pragma unroll
            for (int u = 0; u < 8; u++) {
                const int s = c * 8 + 1 + u;
                float4 ef = reinterpret_cast<const float4*>(sef)[s];
                float n0 = ((a0 * E[0] + a1 * E[4]) + (a2 * E[8]  + a3 * E[12])) * ef.x;
                float n1 = ((a0 * E[1] + a1 * E[5]) + (a2 * E[9]  + a3 * E[13])) * ef.y;
                float n2 = ((a0 * E[2] + a1 * E[6]) + (a2 * E[10] + a3 * E[14])) * ef.z;
                float n3 = ((a0 * E[3] + a1 * E[7]) + (a2 * E[11] + a3 * E[15])) * ef.w;
                a0 = n0; a1 = n1; a2 = n2; a3 = n3;
            }
            float ssum = (a0 + a1) + (a2 + a3);
            lz += __logf(ssum);
            float inv = __fdividef(1.0f, ssum);
            a0 *= inv; a1 *= inv; a2 *= inv; a3 *= inv;
        }
#pragma unroll
        for (int u = 0; u < 7; u++) {            // steps 505..511
            const int s = 505 + u;
            float4 ef = reinterpret_cast<const float4*>(sef)[s];
            float n0 = ((a0 * E[0] + a1 * E[4]) + (a2 * E[8]  + a3 * E[12])) * ef.x;
            float n1 = ((a0 * E[1] + a1 * E[5]) + (a2 * E[9]  + a3 * E[13])) * ef.y;
            float n2 = ((a0 * E[2] + a1 * E[6]) + (a2 * E[10] + a3 * E[14])) * ef.z;
            float n3 = ((a0 * E[3] + a1 * E[7]) + (a2 * E[11] + a3 * E[15])) * ef.w;
            a0 = n0; a1 = n1; a2 = n2; a3 = n3;
        }
        sZ = lz + __logf((a0 * E[3] + a1 * E[7]) + (a2 * E[11] + a3 * E[15]));
    } else if (warp == 1 && lane == 0) {
        // ---- Viterbi forward with packed backpointers, then backtrace ----
        float Tm[16];
#pragma unroll
        for (int i = 0; i < 16; i++) Tm[i] = strn[i];
        float4 f0 = reinterpret_cast<const float4*>(sf)[0];
        float d0 = f0.x + Tm[8],  d1 = f0.y + Tm[9];
        float d2 = f0.z + Tm[10], d3 = f0.w + Tm[11];

#pragma unroll 4
        for (int s = 1; s < S; s++) {
            float4 f = reinterpret_cast<const float4*>(sf)[s];
            int bpw = 0;
#pragma unroll
            for (int j = 0; j < 4; j++) {
                float b0 = d0 + Tm[j], b1 = d1 + Tm[4 + j];
                float b2 = d2 + Tm[8 + j], b3 = d3 + Tm[12 + j];
                float mA = fmaxf(b0, b1); int iA = (b1 > b0) ? 1 : 0;
                float mB = fmaxf(b2, b3); int iB = (b3 > b2) ? 3 : 2;
                float mj = fmaxf(mA, mB); int ij = (mB > mA) ? iB : iA;
                bpw |= ij << (2 * j);
                // stash new value
                if (j == 0) f.x = mj + f.x;
                else if (j == 1) f.y = mj + f.y;
                else if (j == 2) f.z = mj + f.z;
                else f.w = mj + f.w;
            }
            d0 = f.x; d1 = f.y; d2 = f.z; d3 = f.w;
            sbp[s] = bpw;
        }
        // last tag (first-index argmax)
        float v0 = d0 + Tm[3], v1 = d1 + Tm[7], v2 = d2 + Tm[11], v3 = d3 + Tm[15];
        float mA = fmaxf(v0, v1); int iA = (v1 > v0) ? 1 : 0;
        float mB = fmaxf(v2, v3); int iB = (v3 > v2) ? 3 : 2;
        int tag = (mB > mA) ? iB : iA;
        spath[S - 1] = tag;
#pragma unroll 4
        for (int t = S - 1; t >= 1; t--) {
            int w = sbp[t];
            tag = (w >> (2 * tag)) & 3;
            spath[t - 1] = tag;
        }
    } else if (warp == 2) {
        // ---- Gold score + per-batch isqa ----
        float em = 0.f, tr = 0.f;
        for (int s = lane; s < S; s += 32)     em += sf[s * NT + stag[s]];
        for (int s = lane; s < S - 1; s += 32) tr += strn[stag[s] * NT + stag[s + 1]];
        float v = em + tr;
#pragma unroll
        for (int off = 16; off; off >>= 1) v += __shfl_xor_sync(0xFFFFFFFFu, v, off);
        if (lane == 0) {
            sGold = v + strn[TSTART * NT + stag[0]] + strn[stag[S - 1] * NT + TSTOP];
            float l0 = g_logits[b * 2], l1 = g_logits[b * 2 + 1];
            float mm  = fmaxf(l0, l1);
            float lse = mm + __logf(__expf(l0 - mm) + __expf(l1 - mm));
            int y = isqa[b];
            g_iloss[b] = -((y ? l1 : l0) - lse);
            out[OFF_IPRED + b] = (l1 > l0) ? 1.0f : 0.0f;
            out[OFF_ISQA + b] = (float)y;
        }
    }
    __syncthreads();
    if (tid == 0) g_dloss[b] = sZ - sGold;
    for (int i = tid; i < S; i += blockDim.x)
        out[OFF_CPRED + b * S + i] = (float)spath[i];
}

// ---------------------------------------------------------------------------
// Kernel 3: reduce per-batch losses to the two scalar outputs
// ---------------------------------------------------------------------------
__global__ void k_final(float* __restrict__ out) {
    const int tid = threadIdx.x;   // 64 threads
    float d  = g_dloss[tid];
    float il = g_iloss[tid];
#pragma unroll
    for (int off = 16; off; off >>= 1) {
        d  += __shfl_xor_sync(0xFFFFFFFFu, d, off);
        il += __shfl_xor_sync(0xFFFFFFFFu, il, off);
    }
    __shared__ float sd2[2], si2[2];
    if ((tid & 31) == 0) { sd2[tid >> 5] = d; si2[tid >> 5] = il; }
    __syncthreads();
    if (tid == 0) {
        out[OFF_CLOSS] = (sd2[0] + sd2[1]) * (1.0f / 64.0f);
        out[OFF_ILOSS] = (si2[0] + si2[1]) * (1.0f / 64.0f);
    }
}

// ---------------------------------------------------------------------------
extern "C" void kernel_launch(void* const* d_in, const int* in_sizes, int n_in,
                              void* d_out, int out_size) {
    const float* emb    = (const float*)d_in[0];
    const int*   labels = (const int*)d_in[1];
    const int*   isqa   = (const int*)d_in[2];
    const float* fc2_W  = (const float*)d_in[3];
    const float* fc2_b  = (const float*)d_in[4];
    const float* crf_W  = (const float*)d_in[5];
    const float* crf_b  = (const float*)d_in[6];
    const float* trans  = (const float*)d_in[7];
    float* out = (float*)d_out;

    k_feats<<<2052, 256>>>(emb, fc2_W, fc2_b, crf_W, crf_b);
    k_crf<<<B, 128>>>(labels, isqa, trans, out);
    k_final<<<1, 64>>>(out);
}